// round 3
// baseline (speedup 1.0000x reference)
#include <cuda_runtime.h>
#include <math.h>

#define NB    8      // batch rows per CTA
#define NT    256    // threads per CTA
#define NWARP 8

// per-batch-row strides (floats), chosen so (stride mod 32) spreads banks
#define AU_STR  644    // audio rows  (mod 32 = 4)
#define MAG_STR 1068   // mag rows: 132 ic-slots * 8 + pad (mod 32 = 12)
#define E1_STR  1036   // e1 rows: 128 ic * 8 + pad (mod 32 = 12)
#define E2_STR  132    // e2 rows: 64 ic * 2 + pad (mod 32 = 4)
#define E3_STR  68     // e3 rows (mod 32 = 4)
#define XV_STR  132    // x/h/c/y rows (mod 32 = 4)

#define A_FLOATS 8288          // region A: max(8*644, 8*1036)
#define B_FLOATS 8544          // region B: 8*1068
#define SMEM_FLOATS (A_FLOATS + B_FLOATS)

// repacked weights (filled by prep kernel every launch; deterministic)
__device__ float g_w1p[128 * 396];   // [oc][33 blocks][12] 16B-aligned, zero-padded
__device__ float g_w3p[64 * 128];    // [oc][ic][2] taps 1,2 only
__device__ float g_w4p[128 * 64];    // [oc][ic] center tap only

__global__ void prep_kernel(const float* __restrict__ w1,
                            const float* __restrict__ w3,
                            const float* __restrict__ w4) {
    int i = blockIdx.x * blockDim.x + threadIdx.x;
    if (i < 128 * 396) {
        int oc = i / 396, r = i - oc * 396;
        g_w1p[i] = (r < 387) ? w1[oc * 387 + r] : 0.0f;
    }
    if (i < 64 * 128) {
        int oc = i >> 7, r = i & 127;
        int ic = r >> 1, dt = (r & 1) + 1;
        g_w3p[i] = w3[oc * 192 + ic * 3 + dt];
    }
    if (i < 128 * 64) {
        int oc = i >> 6, ic = i & 63;
        g_w4p[i] = w4[oc * 192 + ic * 3 + 1];
    }
}

__device__ __forceinline__ float sigm(float x) { return 1.0f / (1.0f + __expf(-x)); }

__global__ __launch_bounds__(NT, 3) void vad_fused_kernel(
    const float* __restrict__ audio, const float* __restrict__ h_in, const float* __restrict__ c_in,
    const float* __restrict__ basis,
    const float* __restrict__ b1,
    const float* __restrict__ w2, const float* __restrict__ b2,
    const float* __restrict__ b3, const float* __restrict__ b4,
    const float* __restrict__ wi, const float* __restrict__ wf,
    const float* __restrict__ wg, const float* __restrict__ wo,
    const float* __restrict__ ui, const float* __restrict__ uf,
    const float* __restrict__ ug, const float* __restrict__ uo,
    const float* __restrict__ bxi, const float* __restrict__ bxf,
    const float* __restrict__ bxg, const float* __restrict__ bxo,
    const float* __restrict__ bhi, const float* __restrict__ bhf,
    const float* __restrict__ bhg, const float* __restrict__ bho,
    const float* __restrict__ convw, const float* __restrict__ convb,
    float* __restrict__ out, int Btot)
{
    extern __shared__ float sm[];
    float* smA = sm;                 // audio -> e1
    float* smB = sm + A_FLOATS;      // mag -> {e2, e3, x, h, c, y}
    float* s_e2 = smB;
    float* s_e3 = smB + 1056;
    float* s_x  = smB + 1600;
    float* s_h  = smB + 2656;
    float* s_c  = smB + 3712;
    float* s_y  = smB + 4768;

    const int tid  = threadIdx.x;
    const int warp = tid >> 5;
    const int lane = tid & 31;
    const int b0   = blockIdx.x * NB;

    // ---------- phase 0: zero mag region; load reflect-padded audio ----------
    for (int i = tid; i < B_FLOATS; i += NT) smB[i] = 0.0f;
    for (int idx = tid; idx < NB * 640; idx += NT) {
        int b = idx / 640, j = idx - b * 640;
        int gb = b0 + b;
        float v = 0.0f;
        if (gb < Btot) {
            int src = (j < 576) ? j : (1150 - j);
            v = audio[gb * 576 + src];
        }
        smA[b * AU_STR + j] = v;
    }
    __syncthreads();

    // ---------- phase 1: STFT (stride 128, 4 frames) + magnitude ----------
    {
        int b = lane & 7, fr = lane >> 3;                 // lane = fr*8 + b
        const float* au = smA + b * AU_STR + fr * 128;
        for (int ch = warp; ch < 129; ch += NWARP) {
            const float4* br = reinterpret_cast<const float4*>(basis + ch * 256);
            const float4* bi = reinterpret_cast<const float4*>(basis + (ch + 129) * 256);
            float ar = 0.0f, aim = 0.0f;
            #pragma unroll 4
            for (int k = 0; k < 64; k++) {
                float4 wr = __ldg(br + k);
                float4 wm = __ldg(bi + k);
                float4 a  = *reinterpret_cast<const float4*>(au + k * 4);
                ar  += a.x * wr.x + a.y * wr.y + a.z * wr.z + a.w * wr.w;
                aim += a.x * wm.x + a.y * wm.y + a.z * wm.z + a.w * wm.w;
            }
            smB[b * MAG_STR + ch * 8 + 1 + fr] = sqrtf(ar * ar + aim * aim);
        }
    }
    __syncthreads();

    // ---------- phase 2: enc1 (129->128, K=3, pad1, L=4), 16 oc/lane in regs ----------
    {
        int b = lane & 7, t = lane >> 3;                  // lane = t*8 + b
        const float* m = smB + b * MAG_STR + t;           // cols t..t+2 per ic
        float acc[16];
        #pragma unroll
        for (int i = 0; i < 16; i++) acc[i] = __ldg(b1 + warp * 16 + i);
        const float4* wbase = reinterpret_cast<const float4*>(g_w1p + warp * 16 * 396);
        for (int blk = 0; blk < 33; blk++) {
            float mv[12];
            #pragma unroll
            for (int i2 = 0; i2 < 4; i2++) {
                int off = (blk * 4 + i2) * 8;
                mv[i2 * 3 + 0] = m[off + 0];
                mv[i2 * 3 + 1] = m[off + 1];
                mv[i2 * 3 + 2] = m[off + 2];
            }
            const float4* wp = wbase + blk * 3;
            #pragma unroll
            for (int i = 0; i < 16; i++) {
                float4 q0 = __ldg(wp + i * 99 + 0);
                float4 q1 = __ldg(wp + i * 99 + 1);
                float4 q2 = __ldg(wp + i * 99 + 2);
                acc[i] += mv[0] * q0.x + mv[1]  * q0.y + mv[2]  * q0.z
                        + mv[3] * q0.w + mv[4]  * q1.x + mv[5]  * q1.y
                        + mv[6] * q1.z + mv[7]  * q1.w + mv[8]  * q2.x
                        + mv[9] * q2.y + mv[10] * q2.z + mv[11] * q2.w;
            }
        }
        float* e1 = smA + b * E1_STR;
        #pragma unroll
        for (int i = 0; i < 16; i++) {
            int oc = warp * 16 + i;
            e1[oc * 8 + 1 + t] = fmaxf(acc[i], 0.0f);
            if (t == 0) e1[oc * 8] = 0.0f;                // left pad col
        }
    }
    __syncthreads();

    // ---------- phase 3: enc2 (128->64, K=3, s=2, L:4->2) + stage h,c ----------
    for (int idx = tid; idx < NB * 128; idx += NT) {
        int b = idx >> 7, j = idx & 127;
        int gb = b0 + b;
        float hv = 0.0f, cv = 0.0f;
        if (gb < Btot) { hv = h_in[gb * 128 + j]; cv = c_in[gb * 128 + j]; }
        s_h[b * XV_STR + j] = hv;
        s_c[b * XV_STR + j] = cv;
    }
    {
        int b = lane & 7, t = (lane >> 3) & 1, osub = lane >> 4;   // lane = osub*16 + t*8 + b
        const float* e = smA + b * E1_STR + 2 * t;                  // cols 2t..2t+2 per ic
        float acc[4];
        #pragma unroll
        for (int p = 0; p < 4; p++) acc[p] = __ldg(b2 + warp * 8 + p * 2 + osub);
        for (int blk = 0; blk < 32; blk++) {
            float ev[12];
            #pragma unroll
            for (int i2 = 0; i2 < 4; i2++) {
                int off = (blk * 4 + i2) * 8;
                ev[i2 * 3 + 0] = e[off + 0];
                ev[i2 * 3 + 1] = e[off + 1];
                ev[i2 * 3 + 2] = e[off + 2];
            }
            #pragma unroll
            for (int p = 0; p < 4; p++) {
                const float4* wp = reinterpret_cast<const float4*>(
                    w2 + (warp * 8 + p * 2 + osub) * 384 + blk * 12);
                float4 q0 = __ldg(wp + 0), q1 = __ldg(wp + 1), q2 = __ldg(wp + 2);
                acc[p] += ev[0] * q0.x + ev[1]  * q0.y + ev[2]  * q0.z
                        + ev[3] * q0.w + ev[4]  * q1.x + ev[5]  * q1.y
                        + ev[6] * q1.z + ev[7]  * q1.w + ev[8]  * q2.x
                        + ev[9] * q2.y + ev[10] * q2.z + ev[11] * q2.w;
            }
        }
        #pragma unroll
        for (int p = 0; p < 4; p++)
            s_e2[b * E2_STR + (warp * 8 + p * 2 + osub) * 2 + t] = fmaxf(acc[p], 0.0f);
    }
    __syncthreads();

    // ---------- phase 4: enc3 (64->64, s=2, only taps 1,2 valid) ----------
    {
        int b = lane & 7, osub = lane >> 3;               // osub 0..3
        float acc0 = __ldg(b3 + warp * 8 + osub);
        float acc1 = __ldg(b3 + warp * 8 + 4 + osub);
        const float* e2 = s_e2 + b * E2_STR;
        for (int blk = 0; blk < 16; blk++) {
            float d[8];
            #pragma unroll
            for (int i2 = 0; i2 < 4; i2++) {
                d[i2 * 2 + 0] = e2[(blk * 4 + i2) * 2 + 0];
                d[i2 * 2 + 1] = e2[(blk * 4 + i2) * 2 + 1];
            }
            const float4* w0 = reinterpret_cast<const float4*>(
                g_w3p + (warp * 8 + osub) * 128 + blk * 8);
            const float4* w1q = reinterpret_cast<const float4*>(
                g_w3p + (warp * 8 + 4 + osub) * 128 + blk * 8);
            float4 q0 = __ldg(w0 + 0), q1 = __ldg(w0 + 1);
            acc0 += d[0] * q0.x + d[1] * q0.y + d[2] * q0.z + d[3] * q0.w
                  + d[4] * q1.x + d[5] * q1.y + d[6] * q1.z + d[7] * q1.w;
            q0 = __ldg(w1q + 0); q1 = __ldg(w1q + 1);
            acc1 += d[0] * q0.x + d[1] * q0.y + d[2] * q0.z + d[3] * q0.w
                  + d[4] * q1.x + d[5] * q1.y + d[6] * q1.z + d[7] * q1.w;
        }
        s_e3[b * E3_STR + warp * 8 + osub]     = fmaxf(acc0, 0.0f);
        s_e3[b * E3_STR + warp * 8 + 4 + osub] = fmaxf(acc1, 0.0f);
    }
    __syncthreads();

    // ---------- phase 5: enc4 (64->128, center tap only) ----------
    {
        int b = lane & 7, osub = lane >> 3;
        float acc[4];
        #pragma unroll
        for (int g = 0; g < 4; g++) acc[g] = __ldg(b4 + warp * 16 + g * 4 + osub);
        const float* e3 = s_e3 + b * E3_STR;
        for (int blk = 0; blk < 16; blk++) {
            float4 d = *reinterpret_cast<const float4*>(e3 + blk * 4);
            #pragma unroll
            for (int g = 0; g < 4; g++) {
                float4 q = __ldg(reinterpret_cast<const float4*>(
                    g_w4p + (warp * 16 + g * 4 + osub) * 64 + blk * 4));
                acc[g] += d.x * q.x + d.y * q.y + d.z * q.z + d.w * q.w;
            }
        }
        #pragma unroll
        for (int g = 0; g < 4; g++)
            s_x[b * XV_STR + warp * 16 + g * 4 + osub] = fmaxf(acc[g], 0.0f);
    }
    __syncthreads();

    // ---------- phase 6: LSTM cell ----------
    {
        int b = lane & 7, jsub = lane >> 3;               // jsub 0..3
        const float4* xs = reinterpret_cast<const float4*>(s_x + b * XV_STR);
        const float4* hs = reinterpret_cast<const float4*>(s_h + b * XV_STR);
        float* out_h = out + Btot;
        float* out_c = out + Btot + (size_t)Btot * 128;
        #pragma unroll
        for (int jg = 0; jg < 4; jg++) {
            int j = jg * 32 + warp * 4 + jsub;
            float ai = __ldg(bxi + j) + __ldg(bhi + j);
            float af = __ldg(bxf + j) + __ldg(bhf + j);
            float ag = __ldg(bxg + j) + __ldg(bhg + j);
            float ao = __ldg(bxo + j) + __ldg(bho + j);
            const float4* Wi = reinterpret_cast<const float4*>(wi + j * 128);
            const float4* Wf = reinterpret_cast<const float4*>(wf + j * 128);
            const float4* Wg = reinterpret_cast<const float4*>(wg + j * 128);
            const float4* Wo = reinterpret_cast<const float4*>(wo + j * 128);
            const float4* Ui = reinterpret_cast<const float4*>(ui + j * 128);
            const float4* Uf = reinterpret_cast<const float4*>(uf + j * 128);
            const float4* Ug = reinterpret_cast<const float4*>(ug + j * 128);
            const float4* Uo = reinterpret_cast<const float4*>(uo + j * 128);
            #pragma unroll 4
            for (int k = 0; k < 32; k++) {
                float4 xv = xs[k], hv = hs[k];
                float4 q;
                q = __ldg(Wi + k); ai += xv.x * q.x + xv.y * q.y + xv.z * q.z + xv.w * q.w;
                q = __ldg(Wf + k); af += xv.x * q.x + xv.y * q.y + xv.z * q.z + xv.w * q.w;
                q = __ldg(Wg + k); ag += xv.x * q.x + xv.y * q.y + xv.z * q.z + xv.w * q.w;
                q = __ldg(Wo + k); ao += xv.x * q.x + xv.y * q.y + xv.z * q.z + xv.w * q.w;
                q = __ldg(Ui + k); ai += hv.x * q.x + hv.y * q.y + hv.z * q.z + hv.w * q.w;
                q = __ldg(Uf + k); af += hv.x * q.x + hv.y * q.y + hv.z * q.z + hv.w * q.w;
                q = __ldg(Ug + k); ag += hv.x * q.x + hv.y * q.y + hv.z * q.z + hv.w * q.w;
                q = __ldg(Uo + k); ao += hv.x * q.x + hv.y * q.y + hv.z * q.z + hv.w * q.w;
            }
            float ig = sigm(ai), fg = sigm(af);
            float gg = tanhf(ag), og = sigm(ao);
            float co = fg * s_c[b * XV_STR + j] + ig * gg;
            float ho = og * tanhf(co);
            int gb = b0 + b;
            if (gb < Btot) {
                out_h[(size_t)gb * 128 + j] = ho;
                out_c[(size_t)gb * 128 + j] = co;
            }
            s_y[b * XV_STR + j] = fmaxf(ho, 0.0f) * __ldg(convw + j);
        }
    }
    __syncthreads();

    // ---------- phase 7: head reduction (warp w <-> batch row w) ----------
    {
        float s = s_y[warp * XV_STR + lane]      + s_y[warp * XV_STR + lane + 32]
                + s_y[warp * XV_STR + lane + 64] + s_y[warp * XV_STR + lane + 96];
        #pragma unroll
        for (int off = 16; off > 0; off >>= 1)
            s += __shfl_down_sync(0xffffffffu, s, off);
        if (lane == 0) {
            int gb = b0 + warp;
            if (gb < Btot)
                out[gb] = 1.0f / (1.0f + __expf(-(s + __ldg(convb))));
        }
    }
}

extern "C" void kernel_launch(void* const* d_in, const int* in_sizes, int n_in,
                              void* d_out, int out_size) {
    const float* audio = (const float*)d_in[0];
    const float* h_in  = (const float*)d_in[1];
    const float* c_in  = (const float*)d_in[2];
    const float* basis = (const float*)d_in[3];
    const float* w1 = (const float*)d_in[4];  const float* b1 = (const float*)d_in[5];
    const float* w2 = (const float*)d_in[6];  const float* b2 = (const float*)d_in[7];
    const float* w3 = (const float*)d_in[8];  const float* b3 = (const float*)d_in[9];
    const float* w4 = (const float*)d_in[10]; const float* b4 = (const float*)d_in[11];
    const float* wi = (const float*)d_in[12]; const float* wf = (const float*)d_in[13];
    const float* wg = (const float*)d_in[14]; const float* wo = (const float*)d_in[15];
    const float* ui = (const float*)d_in[16]; const float* uf = (const float*)d_in[17];
    const float* ug = (const float*)d_in[18]; const float* uo = (const float*)d_in[19];
    const float* bxi = (const float*)d_in[20]; const float* bxf = (const float*)d_in[21];
    const float* bxg = (const float*)d_in[22]; const float* bxo = (const float*)d_in[23];
    const float* bhi = (const float*)d_in[24]; const float* bhf = (const float*)d_in[25];
    const float* bhg = (const float*)d_in[26]; const float* bho = (const float*)d_in[27];
    const float* convw = (const float*)d_in[28]; const float* convb = (const float*)d_in[29];

    int Btot = in_sizes[0] / 576;
    int grid = (Btot + NB - 1) / NB;
    size_t smem_bytes = SMEM_FLOATS * sizeof(float);   // ~67 KB
    cudaFuncSetAttribute(vad_fused_kernel,
                         cudaFuncAttributeMaxDynamicSharedMemorySize, (int)smem_bytes);

    prep_kernel<<<(128 * 396 + NT - 1) / NT, NT>>>(w1, w3, w4);
    vad_fused_kernel<<<grid, NT, smem_bytes>>>(
        audio, h_in, c_in, basis,
        b1, w2, b2, b3, b4,
        wi, wf, wg, wo, ui, uf, ug, uo,
        bxi, bxf, bxg, bxo, bhi, bhf, bhg, bho,
        convw, convb,
        (float*)d_out, Btot);
}

// round 4
// speedup vs baseline: 1.0137x; 1.0137x over previous
#include <cuda_runtime.h>
#include <math.h>

#define NB    8      // batch rows per CTA
#define NT    256    // threads per CTA
#define NWARP 8

typedef unsigned long long u64;

// per-batch-row strides (floats), chosen so (stride mod 32) spreads banks
#define AU_STR  644    // audio rows  (mod 32 = 4), 16B-aligned
#define MAG_STR 1068   // mag rows: 132 ic-slots * 8 + pad (mod 32 = 12)
#define E1_STR  1036   // e1 rows: 128 ic * 8 + pad (mod 32 = 12)
#define E2_STR  132    // e2 rows: 64 ic * 2 + pad (mod 32 = 4), 16B-aligned
#define E3_STR  68     // e3 rows (mod 32 = 4), 16B-aligned
#define XV_STR  132    // x/h/c/y rows (mod 32 = 4), 16B-aligned

#define A_FLOATS 8288          // region A: max(8*644, 8*1036)
#define B_FLOATS 8544          // region B: 8*1068
#define SMEM_FLOATS (A_FLOATS + B_FLOATS)

// repacked weights (filled by prep kernel every launch; deterministic)
__device__ float g_w1p[128 * 396];   // [oc][33 blocks][12] 16B-aligned, zero-padded
__device__ float g_w3p[64 * 128];    // [oc][ic][2] taps 1,2 only
__device__ float g_w4p[128 * 64];    // [oc][ic] center tap only

__global__ void prep_kernel(const float* __restrict__ w1,
                            const float* __restrict__ w3,
                            const float* __restrict__ w4) {
    int i = blockIdx.x * blockDim.x + threadIdx.x;
    if (i < 128 * 396) {
        int oc = i / 396, r = i - oc * 396;
        g_w1p[i] = (r < 387) ? w1[oc * 387 + r] : 0.0f;
    }
    if (i < 64 * 128) {
        int oc = i >> 7, r = i & 127;
        int ic = r >> 1, dt = (r & 1) + 1;
        g_w3p[i] = w3[oc * 192 + ic * 3 + dt];
    }
    if (i < 128 * 64) {
        int oc = i >> 6, ic = i & 63;
        g_w4p[i] = w4[oc * 192 + ic * 3 + 1];
    }
}

// ---- packed fp32x2 helpers (sm_103a FFMA2 path; ptxas never emits it from C++) ----
__device__ __forceinline__ u64 f2fma(u64 a, u64 b, u64 c) {
    u64 d;
    asm("fma.rn.f32x2 %0, %1, %2, %3;" : "=l"(d) : "l"(a), "l"(b), "l"(c));
    return d;
}
__device__ __forceinline__ u64 f2pack(float x, float y) {
    u64 d;
    asm("mov.b64 %0, {%1, %2};" : "=l"(d) : "f"(x), "f"(y));
    return d;
}
__device__ __forceinline__ float f2sum(u64 v) {
    float x, y;
    asm("mov.b64 {%0, %1}, %2;" : "=f"(x), "=f"(y) : "l"(v));
    return x + y;
}

__device__ __forceinline__ float sigm(float x) { return 1.0f / (1.0f + __expf(-x)); }

__global__ __launch_bounds__(NT, 2) void vad_fused_kernel(
    const float* __restrict__ audio, const float* __restrict__ h_in, const float* __restrict__ c_in,
    const float* __restrict__ basis,
    const float* __restrict__ b1,
    const float* __restrict__ w2, const float* __restrict__ b2,
    const float* __restrict__ b3, const float* __restrict__ b4,
    const float* __restrict__ wi, const float* __restrict__ wf,
    const float* __restrict__ wg, const float* __restrict__ wo,
    const float* __restrict__ ui, const float* __restrict__ uf,
    const float* __restrict__ ug, const float* __restrict__ uo,
    const float* __restrict__ bxi, const float* __restrict__ bxf,
    const float* __restrict__ bxg, const float* __restrict__ bxo,
    const float* __restrict__ bhi, const float* __restrict__ bhf,
    const float* __restrict__ bhg, const float* __restrict__ bho,
    const float* __restrict__ convw, const float* __restrict__ convb,
    float* __restrict__ out, int Btot)
{
    extern __shared__ float sm[];
    float* smA = sm;                 // audio -> e1
    float* smB = sm + A_FLOATS;      // mag -> {e2, e3, x, h, c, y}
    float* s_e2 = smB;
    float* s_e3 = smB + 1056;
    float* s_x  = smB + 1600;
    float* s_h  = smB + 2656;
    float* s_c  = smB + 3712;
    float* s_y  = smB + 4768;

    const int tid  = threadIdx.x;
    const int warp = tid >> 5;
    const int lane = tid & 31;
    const int b0   = blockIdx.x * NB;

    // ---------- phase 0: zero mag region; load reflect-padded audio ----------
    for (int i = tid; i < B_FLOATS; i += NT) smB[i] = 0.0f;
    for (int idx = tid; idx < NB * 640; idx += NT) {
        int b = idx / 640, j = idx - b * 640;
        int gb = b0 + b;
        float v = 0.0f;
        if (gb < Btot) {
            int src = (j < 576) ? j : (1150 - j);
            v = audio[gb * 576 + src];
        }
        smA[b * AU_STR + j] = v;
    }
    __syncthreads();

    // ---------- phase 1: STFT (stride 128, 4 frames) + magnitude ----------
    {
        int b = lane & 7, fr = lane >> 3;                 // lane = fr*8 + b
        const ulonglong2* ap = reinterpret_cast<const ulonglong2*>(smA + b * AU_STR + fr * 128);
        for (int ch = warp; ch < 129; ch += NWARP) {
            const ulonglong2* br = reinterpret_cast<const ulonglong2*>(basis + ch * 256);
            const ulonglong2* bi = reinterpret_cast<const ulonglong2*>(basis + (ch + 129) * 256);
            u64 sR0 = 0ull, sR1 = 0ull, sI0 = 0ull, sI1 = 0ull;
            #pragma unroll 4
            for (int k = 0; k < 64; k++) {
                ulonglong2 wr = __ldg(br + k);
                ulonglong2 wm = __ldg(bi + k);
                ulonglong2 a  = ap[k];
                sR0 = f2fma(a.x, wr.x, sR0);
                sR1 = f2fma(a.y, wr.y, sR1);
                sI0 = f2fma(a.x, wm.x, sI0);
                sI1 = f2fma(a.y, wm.y, sI1);
            }
            float ar  = f2sum(sR0) + f2sum(sR1);
            float aim = f2sum(sI0) + f2sum(sI1);
            smB[b * MAG_STR + ch * 8 + 1 + fr] = sqrtf(ar * ar + aim * aim);
        }
    }
    __syncthreads();

    // ---------- phase 2: enc1 (129->128, K=3, pad1, L=4), 16 oc/lane, f32x2 ----------
    {
        int b = lane & 7, t = lane >> 3;                  // lane = t*8 + b
        const float* m = smB + b * MAG_STR + t;           // cols t..t+2 per ic
        u64 acc[16];
        #pragma unroll
        for (int i = 0; i < 16; i++) acc[i] = f2pack(__ldg(b1 + warp * 16 + i), 0.0f);
        const float* wbase = g_w1p + warp * 16 * 396;
        for (int blk = 0; blk < 33; blk++) {
            float mv[12];
            #pragma unroll
            for (int i2 = 0; i2 < 4; i2++) {
                int off = (blk * 4 + i2) * 8;
                mv[i2 * 3 + 0] = m[off + 0];
                mv[i2 * 3 + 1] = m[off + 1];
                mv[i2 * 3 + 2] = m[off + 2];
            }
            u64 mp[6];
            #pragma unroll
            for (int q = 0; q < 6; q++) mp[q] = f2pack(mv[2 * q], mv[2 * q + 1]);
            #pragma unroll
            for (int i = 0; i < 16; i++) {
                const ulonglong2* wp = reinterpret_cast<const ulonglong2*>(wbase + i * 396 + blk * 12);
                ulonglong2 q0 = __ldg(wp + 0);
                ulonglong2 q1 = __ldg(wp + 1);
                ulonglong2 q2 = __ldg(wp + 2);
                u64 a = acc[i];
                a = f2fma(mp[0], q0.x, a);
                a = f2fma(mp[1], q0.y, a);
                a = f2fma(mp[2], q1.x, a);
                a = f2fma(mp[3], q1.y, a);
                a = f2fma(mp[4], q2.x, a);
                a = f2fma(mp[5], q2.y, a);
                acc[i] = a;
            }
        }
        float* e1 = smA + b * E1_STR;
        #pragma unroll
        for (int i = 0; i < 16; i++) {
            int oc = warp * 16 + i;
            e1[oc * 8 + 1 + t] = fmaxf(f2sum(acc[i]), 0.0f);
            if (t == 0) e1[oc * 8] = 0.0f;                // left pad col
        }
    }
    __syncthreads();

    // ---------- phase 3: enc2 (128->64, K=3, s=2, L:4->2) + stage h,c ----------
    for (int idx = tid; idx < NB * 128; idx += NT) {
        int b = idx >> 7, j = idx & 127;
        int gb = b0 + b;
        float hv = 0.0f, cv = 0.0f;
        if (gb < Btot) { hv = h_in[gb * 128 + j]; cv = c_in[gb * 128 + j]; }
        s_h[b * XV_STR + j] = hv;
        s_c[b * XV_STR + j] = cv;
    }
    {
        int b = lane & 7, t = (lane >> 3) & 1, osub = lane >> 4;   // lane = osub*16 + t*8 + b
        const float* e = smA + b * E1_STR + 2 * t;                  // cols 2t..2t+2 per ic
        u64 acc[4];
        #pragma unroll
        for (int p = 0; p < 4; p++) acc[p] = f2pack(__ldg(b2 + warp * 8 + p * 2 + osub), 0.0f);
        for (int blk = 0; blk < 32; blk++) {
            float ev[12];
            #pragma unroll
            for (int i2 = 0; i2 < 4; i2++) {
                int off = (blk * 4 + i2) * 8;
                ev[i2 * 3 + 0] = e[off + 0];
                ev[i2 * 3 + 1] = e[off + 1];
                ev[i2 * 3 + 2] = e[off + 2];
            }
            u64 ep[6];
            #pragma unroll
            for (int q = 0; q < 6; q++) ep[q] = f2pack(ev[2 * q], ev[2 * q + 1]);
            #pragma unroll
            for (int p = 0; p < 4; p++) {
                const ulonglong2* wp = reinterpret_cast<const ulonglong2*>(
                    w2 + (warp * 8 + p * 2 + osub) * 384 + blk * 12);
                ulonglong2 q0 = __ldg(wp + 0);
                ulonglong2 q1 = __ldg(wp + 1);
                ulonglong2 q2 = __ldg(wp + 2);
                u64 a = acc[p];
                a = f2fma(ep[0], q0.x, a);
                a = f2fma(ep[1], q0.y, a);
                a = f2fma(ep[2], q1.x, a);
                a = f2fma(ep[3], q1.y, a);
                a = f2fma(ep[4], q2.x, a);
                a = f2fma(ep[5], q2.y, a);
                acc[p] = a;
            }
        }
        #pragma unroll
        for (int p = 0; p < 4; p++)
            s_e2[b * E2_STR + (warp * 8 + p * 2 + osub) * 2 + t] = fmaxf(f2sum(acc[p]), 0.0f);
    }
    __syncthreads();

    // ---------- phase 4: enc3 (64->64, s=2, only taps 1,2 valid), f32x2 ----------
    {
        int b = lane & 7, osub = lane >> 3;               // osub 0..3
        u64 A0 = f2pack(__ldg(b3 + warp * 8 + osub), 0.0f);
        u64 A1 = f2pack(__ldg(b3 + warp * 8 + 4 + osub), 0.0f);
        const float* e2 = s_e2 + b * E2_STR;
        for (int blk = 0; blk < 16; blk++) {
            ulonglong2 dA = *reinterpret_cast<const ulonglong2*>(e2 + blk * 8);
            ulonglong2 dB = *reinterpret_cast<const ulonglong2*>(e2 + blk * 8 + 4);
            const ulonglong2* w0 = reinterpret_cast<const ulonglong2*>(
                g_w3p + (warp * 8 + osub) * 128 + blk * 8);
            const ulonglong2* w1q = reinterpret_cast<const ulonglong2*>(
                g_w3p + (warp * 8 + 4 + osub) * 128 + blk * 8);
            ulonglong2 qa = __ldg(w0 + 0), qb = __ldg(w0 + 1);
            A0 = f2fma(dA.x, qa.x, A0);
            A0 = f2fma(dA.y, qa.y, A0);
            A0 = f2fma(dB.x, qb.x, A0);
            A0 = f2fma(dB.y, qb.y, A0);
            qa = __ldg(w1q + 0); qb = __ldg(w1q + 1);
            A1 = f2fma(dA.x, qa.x, A1);
            A1 = f2fma(dA.y, qa.y, A1);
            A1 = f2fma(dB.x, qb.x, A1);
            A1 = f2fma(dB.y, qb.y, A1);
        }
        s_e3[b * E3_STR + warp * 8 + osub]     = fmaxf(f2sum(A0), 0.0f);
        s_e3[b * E3_STR + warp * 8 + 4 + osub] = fmaxf(f2sum(A1), 0.0f);
    }
    __syncthreads();

    // ---------- phase 5: enc4 (64->128, center tap only), f32x2 ----------
    {
        int b = lane & 7, osub = lane >> 3;
        u64 A[4];
        #pragma unroll
        for (int g = 0; g < 4; g++) A[g] = f2pack(__ldg(b4 + warp * 16 + g * 4 + osub), 0.0f);
        const float* e3 = s_e3 + b * E3_STR;
        for (int blk = 0; blk < 16; blk++) {
            ulonglong2 d = *reinterpret_cast<const ulonglong2*>(e3 + blk * 4);
            #pragma unroll
            for (int g = 0; g < 4; g++) {
                ulonglong2 q = __ldg(reinterpret_cast<const ulonglong2*>(
                    g_w4p + (warp * 16 + g * 4 + osub) * 64 + blk * 4));
                A[g] = f2fma(d.x, q.x, A[g]);
                A[g] = f2fma(d.y, q.y, A[g]);
            }
        }
        #pragma unroll
        for (int g = 0; g < 4; g++)
            s_x[b * XV_STR + warp * 16 + g * 4 + osub] = fmaxf(f2sum(A[g]), 0.0f);
    }
    __syncthreads();

    // ---------- phase 6: LSTM cell, f32x2 ----------
    {
        int b = lane & 7, jsub = lane >> 3;               // jsub 0..3
        const ulonglong2* xs = reinterpret_cast<const ulonglong2*>(s_x + b * XV_STR);
        const ulonglong2* hs = reinterpret_cast<const ulonglong2*>(s_h + b * XV_STR);
        float* out_h = out + Btot;
        float* out_c = out + Btot + (size_t)Btot * 128;
        #pragma unroll
        for (int jg = 0; jg < 4; jg++) {
            int j = jg * 32 + warp * 4 + jsub;
            u64 Ai = f2pack(__ldg(bxi + j) + __ldg(bhi + j), 0.0f);
            u64 Af = f2pack(__ldg(bxf + j) + __ldg(bhf + j), 0.0f);
            u64 Ag = f2pack(__ldg(bxg + j) + __ldg(bhg + j), 0.0f);
            u64 Ao = f2pack(__ldg(bxo + j) + __ldg(bho + j), 0.0f);
            const ulonglong2* Wi = reinterpret_cast<const ulonglong2*>(wi + j * 128);
            const ulonglong2* Wf = reinterpret_cast<const ulonglong2*>(wf + j * 128);
            const ulonglong2* Wg = reinterpret_cast<const ulonglong2*>(wg + j * 128);
            const ulonglong2* Wo = reinterpret_cast<const ulonglong2*>(wo + j * 128);
            const ulonglong2* Ui = reinterpret_cast<const ulonglong2*>(ui + j * 128);
            const ulonglong2* Uf = reinterpret_cast<const ulonglong2*>(uf + j * 128);
            const ulonglong2* Ug = reinterpret_cast<const ulonglong2*>(ug + j * 128);
            const ulonglong2* Uo = reinterpret_cast<const ulonglong2*>(uo + j * 128);
            #pragma unroll 4
            for (int k = 0; k < 32; k++) {
                ulonglong2 xv = xs[k], hv = hs[k];
                ulonglong2 q;
                q = __ldg(Wi + k); Ai = f2fma(xv.x, q.x, Ai); Ai = f2fma(xv.y, q.y, Ai);
                q = __ldg(Wf + k); Af = f2fma(xv.x, q.x, Af); Af = f2fma(xv.y, q.y, Af);
                q = __ldg(Wg + k); Ag = f2fma(xv.x, q.x, Ag); Ag = f2fma(xv.y, q.y, Ag);
                q = __ldg(Wo + k); Ao = f2fma(xv.x, q.x, Ao); Ao = f2fma(xv.y, q.y, Ao);
                q = __ldg(Ui + k); Ai = f2fma(hv.x, q.x, Ai); Ai = f2fma(hv.y, q.y, Ai);
                q = __ldg(Uf + k); Af = f2fma(hv.x, q.x, Af); Af = f2fma(hv.y, q.y, Af);
                q = __ldg(Ug + k); Ag = f2fma(hv.x, q.x, Ag); Ag = f2fma(hv.y, q.y, Ag);
                q = __ldg(Uo + k); Ao = f2fma(hv.x, q.x, Ao); Ao = f2fma(hv.y, q.y, Ao);
            }
            float ig = sigm(f2sum(Ai)), fg = sigm(f2sum(Af));
            float gg = tanhf(f2sum(Ag)), og = sigm(f2sum(Ao));
            float co = fg * s_c[b * XV_STR + j] + ig * gg;
            float ho = og * tanhf(co);
            int gb = b0 + b;
            if (gb < Btot) {
                out_h[(size_t)gb * 128 + j] = ho;
                out_c[(size_t)gb * 128 + j] = co;
            }
            s_y[b * XV_STR + j] = fmaxf(ho, 0.0f) * __ldg(convw + j);
        }
    }
    __syncthreads();

    // ---------- phase 7: head reduction (warp w <-> batch row w) ----------
    {
        float s = s_y[warp * XV_STR + lane]      + s_y[warp * XV_STR + lane + 32]
                + s_y[warp * XV_STR + lane + 64] + s_y[warp * XV_STR + lane + 96];
        #pragma unroll
        for (int off = 16; off > 0; off >>= 1)
            s += __shfl_down_sync(0xffffffffu, s, off);
        if (lane == 0) {
            int gb = b0 + warp;
            if (gb < Btot)
                out[gb] = 1.0f / (1.0f + __expf(-(s + __ldg(convb))));
        }
    }
}

extern "C" void kernel_launch(void* const* d_in, const int* in_sizes, int n_in,
                              void* d_out, int out_size) {
    const float* audio = (const float*)d_in[0];
    const float* h_in  = (const float*)d_in[1];
    const float* c_in  = (const float*)d_in[2];
    const float* basis = (const float*)d_in[3];
    const float* w1 = (const float*)d_in[4];  const float* b1 = (const float*)d_in[5];
    const float* w2 = (const float*)d_in[6];  const float* b2 = (const float*)d_in[7];
    const float* w3 = (const float*)d_in[8];  const float* b3 = (const float*)d_in[9];
    const float* w4 = (const float*)d_in[10]; const float* b4 = (const float*)d_in[11];
    const float* wi = (const float*)d_in[12]; const float* wf = (const float*)d_in[13];
    const float* wg = (const float*)d_in[14]; const float* wo = (const float*)d_in[15];
    const float* ui = (const float*)d_in[16]; const float* uf = (const float*)d_in[17];
    const float* ug = (const float*)d_in[18]; const float* uo = (const float*)d_in[19];
    const float* bxi = (const float*)d_in[20]; const float* bxf = (const float*)d_in[21];
    const float* bxg = (const float*)d_in[22]; const float* bxo = (const float*)d_in[23];
    const float* bhi = (const float*)d_in[24]; const float* bhf = (const float*)d_in[25];
    const float* bhg = (const float*)d_in[26]; const float* bho = (const float*)d_in[27];
    const float* convw = (const float*)d_in[28]; const float* convb = (const float*)d_in[29];

    int Btot = in_sizes[0] / 576;
    int grid = (Btot + NB - 1) / NB;
    size_t smem_bytes = SMEM_FLOATS * sizeof(float);   // ~67 KB
    cudaFuncSetAttribute(vad_fused_kernel,
                         cudaFuncAttributeMaxDynamicSharedMemorySize, (int)smem_bytes);

    prep_kernel<<<(128 * 396 + NT - 1) / NT, NT>>>(w1, w3, w4);
    vad_fused_kernel<<<grid, NT, smem_bytes>>>(
        audio, h_in, c_in, basis,
        b1, w2, b2, b3, b4,
        wi, wf, wg, wo, ui, uf, ug, uo,
        bxi, bxf, bxg, bxo, bhi, bhf, bhg, bho,
        convw, convb,
        (float*)d_out, Btot);
}